// round 1
// baseline (speedup 1.0000x reference)
#include <cuda_runtime.h>
#include <math.h>

// ---------------------------------------------------------------------------
// YOLOv8 head: per level L in {p3,p4,p5}:
//   y = relu(conv3x3(x, w1)*s1 + b1)
//   y = relu(conv3x3(y, w2)*s2 + b2)
//   o5 = conv1x1(y, wf) + bf        (5 output channels)
//   decode boxes with anchors/strides, sigmoid on cls channel
// Output: (B, 5, 33600) fp32, levels concatenated along anchor dim.
// ---------------------------------------------------------------------------

#define TS  16      // spatial tile (TS x TS output pixels per block)
#define COT 16      // output channels per block
#define ATOT 33600  // 160*160 + 80*80 + 40*40

// Static scratch (max level: B=8, C=128, 160x160 = 26.2M floats each)
__device__ float g_buf1[8 * 128 * 160 * 160];
__device__ float g_buf2[8 * 128 * 160 * 160];

// ---------------------------------------------------------------------------
// conv3x3 (pad 1, stride 1) + per-channel scale/bias + ReLU.
// grid: (tilesX*tilesY, C/COT, B), block: 256 threads (16x16 pixels).
// Each thread: 1 output pixel x 16 output channels (register accumulators).
// ---------------------------------------------------------------------------
__global__ void __launch_bounds__(256)
conv3x3_bn_relu_kernel(const float* __restrict__ in,
                       const float* __restrict__ wgt,   // (C_out, C_in, 3, 3)
                       const float* __restrict__ scale,
                       const float* __restrict__ bias,
                       float* __restrict__ out,
                       int C, int H, int W, int tilesX)
{
    const int tile = blockIdx.x;
    const int tx0 = (tile % tilesX) * TS;
    const int ty0 = (tile / tilesX) * TS;
    const int co0 = blockIdx.y * COT;
    const int n   = blockIdx.z;

    const int lx = threadIdx.x & (TS - 1);
    const int ly = threadIdx.x >> 4;
    const int ox = tx0 + lx;
    const int oy = ty0 + ly;

    __shared__ float s_in[18][19];   // 16+2 halo, padded row to soften conflicts
    __shared__ float s_w[COT][9];

    float acc[COT];
#pragma unroll
    for (int i = 0; i < COT; i++) acc[i] = 0.f;

    const float* inN = in + (size_t)n * C * H * W;
    const float* wco = wgt + (size_t)co0 * C * 9;

    for (int ci = 0; ci < C; ci++) {
        const float* inC = inN + (size_t)ci * H * W;

        // load 18x18 input patch (zero-padded at image borders)
        for (int t = threadIdx.x; t < 18 * 18; t += 256) {
            int py = t / 18, px = t - py * 18;
            int gy = ty0 + py - 1, gx = tx0 + px - 1;
            float v = 0.f;
            if ((unsigned)gy < (unsigned)H && (unsigned)gx < (unsigned)W)
                v = inC[gy * W + gx];
            s_in[py][px] = v;
        }
        // load 16 co x 9 weights for this ci
        if (threadIdx.x < COT * 9) {
            int co = threadIdx.x / 9, k = threadIdx.x - co * 9;
            s_w[co][k] = wco[(size_t)co * C * 9 + ci * 9 + k];
        }
        __syncthreads();

        float r[9];
#pragma unroll
        for (int ky = 0; ky < 3; ky++)
#pragma unroll
            for (int kx = 0; kx < 3; kx++)
                r[ky * 3 + kx] = s_in[ly + ky][lx + kx];

#pragma unroll
        for (int co = 0; co < COT; co++) {
            float a = acc[co];
#pragma unroll
            for (int k = 0; k < 9; k++) a = fmaf(r[k], s_w[co][k], a);
            acc[co] = a;
        }
        __syncthreads();
    }

    if (ox < W && oy < H) {
        size_t o = (((size_t)n * C + co0) * H + oy) * W + ox;
        const size_t chs = (size_t)H * W;
#pragma unroll
        for (int co = 0; co < COT; co++) {
            float v = fmaf(acc[co], scale[co0 + co], bias[co0 + co]);
            out[o + (size_t)co * chs] = fmaxf(v, 0.f);
        }
    }
}

// ---------------------------------------------------------------------------
// conv1x1 (C -> 5) + bias + anchor decode + sigmoid, writes directly into
// the (B, 5, ATOT) output at anchor offset `aoff`.
// ---------------------------------------------------------------------------
__global__ void __launch_bounds__(256)
conv1x1_decode_kernel(const float* __restrict__ y,
                      const float* __restrict__ wf,   // (5, C)
                      const float* __restrict__ bf,   // (5,)
                      float* __restrict__ out,
                      int C, int W, int HW, int aoff, float stride)
{
    extern __shared__ float s_wf[];  // 5*C floats
    for (int t = threadIdx.x; t < 5 * C; t += blockDim.x)
        s_wf[t] = wf[t];
    __syncthreads();

    const int p = blockIdx.x * blockDim.x + threadIdx.x;
    const int n = blockIdx.y;
    if (p >= HW) return;

    const float* yp = y + (size_t)n * C * HW + p;
    float a0 = bf[0], a1 = bf[1], a2 = bf[2], a3 = bf[3], a4 = bf[4];
    for (int ci = 0; ci < C; ci++) {
        float v = yp[(size_t)ci * HW];
        a0 = fmaf(v, s_wf[ci],         a0);
        a1 = fmaf(v, s_wf[C + ci],     a1);
        a2 = fmaf(v, s_wf[2 * C + ci], a2);
        a3 = fmaf(v, s_wf[3 * C + ci], a3);
        a4 = fmaf(v, s_wf[4 * C + ci], a4);
    }

    // decode: lt=(a0,a1), rb=(a2,a3); anchor = (px+0.5, py+0.5)
    const int py = p / W;
    const int px = p - py * W;
    const float ax = px + 0.5f, ay = py + 0.5f;
    const float cx = (ax + 0.5f * (a2 - a0)) * stride;
    const float cy = (ay + 0.5f * (a3 - a1)) * stride;
    const float bw = (a2 + a0) * stride;
    const float bh = (a3 + a1) * stride;
    const float cls = 1.f / (1.f + expf(-a4));

    size_t base = (size_t)n * 5 * ATOT + (size_t)aoff + p;
    out[base]                    = cx;
    out[base + (size_t)ATOT]     = cy;
    out[base + 2 * (size_t)ATOT] = bw;
    out[base + 3 * (size_t)ATOT] = bh;
    out[base + 4 * (size_t)ATOT] = cls;
}

// ---------------------------------------------------------------------------
// Host side
// ---------------------------------------------------------------------------
static void run_head(const float* x, void* const* d_in, int widx,
                     float* buf1, float* buf2, float* out,
                     int B, int C, int H, int aoff, float stride)
{
    const float* w1 = (const float*)d_in[widx + 0];
    const float* s1 = (const float*)d_in[widx + 1];
    const float* b1 = (const float*)d_in[widx + 2];
    const float* w2 = (const float*)d_in[widx + 3];
    const float* s2 = (const float*)d_in[widx + 4];
    const float* b2 = (const float*)d_in[widx + 5];
    const float* wf = (const float*)d_in[widx + 6];
    const float* bf = (const float*)d_in[widx + 7];

    const int W = H;
    const int tilesX = (W + TS - 1) / TS;
    const int tilesY = (H + TS - 1) / TS;
    dim3 grid(tilesX * tilesY, C / COT, B);

    conv3x3_bn_relu_kernel<<<grid, 256>>>(x,    w1, s1, b1, buf1, C, H, W, tilesX);
    conv3x3_bn_relu_kernel<<<grid, 256>>>(buf1, w2, s2, b2, buf2, C, H, W, tilesX);

    const int HW = H * W;
    dim3 g2((HW + 255) / 256, B);
    conv1x1_decode_kernel<<<g2, 256, 5 * C * (int)sizeof(float)>>>(
        buf2, wf, bf, out, C, W, HW, aoff, stride);
}

extern "C" void kernel_launch(void* const* d_in, const int* in_sizes, int n_in,
                              void* d_out, int out_size)
{
    float *buf1, *buf2;
    cudaGetSymbolAddress((void**)&buf1, g_buf1);
    cudaGetSymbolAddress((void**)&buf2, g_buf2);

    const int B = in_sizes[0] / (128 * 160 * 160);
    float* out = (float*)d_out;

    // level:            x,            widx, C,   H,   aoff,  stride
    run_head((const float*)d_in[0], d_in,  3, buf1, buf2, out, B, 128, 160, 0,     8.f);
    run_head((const float*)d_in[1], d_in, 11, buf1, buf2, out, B, 256,  80, 25600, 16.f);
    run_head((const float*)d_in[2], d_in, 19, buf1, buf2, out, B, 512,  40, 32000, 32.f);
}

// round 2
// speedup vs baseline: 2.1597x; 2.1597x over previous
#include <cuda_runtime.h>
#include <math.h>

// ---------------------------------------------------------------------------
// YOLOv8 head, round 2: register-tiled direct conv (2x2 px * 8 cout / thread).
// Output: (B, 5, 33600) fp32.
// ---------------------------------------------------------------------------

#define ATOT 33600  // 160*160 + 80*80 + 40*40

__device__ float g_buf1[8 * 128 * 160 * 160];
__device__ float g_buf2[8 * 128 * 160 * 160];

// ---------------------------------------------------------------------------
// conv3x3 (pad 1) + scale/bias + ReLU.
// Template tile: TW x TH pixels, CG co-groups of 8 channels => COB = 8*CG.
// threads = (TW/2)*(TH/2)*CG, must equal 256.
// Each thread: 2x2 pixels x 8 output channels, 32 fp32 accumulators.
// ---------------------------------------------------------------------------
template<int TW, int TH, int CG>
__global__ void __launch_bounds__(256)
conv3x3_bn_relu_v2(const float* __restrict__ in,
                   const float* __restrict__ wgt,    // (C, C, 3, 3)
                   const float* __restrict__ scale,
                   const float* __restrict__ bias,
                   float* __restrict__ out,
                   int C, int H, int W, int tilesX)
{
    constexpr int TX  = TW / 2;
    constexpr int TY  = TH / 2;
    constexpr int GRP = TX * TY;         // threads per co-group
    constexpr int COB = CG * 8;          // output channels per block
    constexpr int SW  = TW + 2;
    constexpr int SH  = TH + 2;
    static_assert(GRP * CG == 256, "block must be 256 threads");

    __shared__ float s_in[SH][SW];
    __shared__ __align__(16) float s_w[9][COB];   // [kernel pos][cout]

    const int tile = blockIdx.x;
    const int tx0  = (tile % tilesX) * TW;
    const int ty0  = (tile / tilesX) * TH;
    const int n    = blockIdx.z;
    const int tid  = threadIdx.x;

    const int cg = tid / GRP;
    const int tg = tid - cg * GRP;
    const int tx = tg % TX;
    const int ty = tg / TX;
    const int ox = tx0 + tx * 2;
    const int oy = ty0 + ty * 2;
    const int coBase = blockIdx.y * COB;
    const int coThr  = coBase + cg * 8;

    float acc[8][4];
#pragma unroll
    for (int j = 0; j < 8; j++)
#pragma unroll
        for (int p = 0; p < 4; p++) acc[j][p] = 0.f;

    const float* inN = in + (size_t)n * C * H * W;
    const float* wB  = wgt + (size_t)coBase * C * 9;

    for (int ci = 0; ci < C; ci++) {
        const float* inC = inN + (size_t)ci * H * W;

        // cooperative load of (TH+2)x(TW+2) input patch, zero-padded
#pragma unroll 1
        for (int t = tid; t < SH * SW; t += 256) {
            int py = t / SW, px = t - py * SW;
            int gy = ty0 + py - 1, gx = tx0 + px - 1;
            float v = 0.f;
            if ((unsigned)gy < (unsigned)H && (unsigned)gx < (unsigned)W)
                v = inC[gy * W + gx];
            s_in[py][px] = v;
        }
        // weights for this ci: s_w[k][co]
#pragma unroll 1
        for (int t = tid; t < 9 * COB; t += 256) {
            int co = t / 9, k = t - co * 9;
            s_w[k][co] = wB[(size_t)co * C * 9 + (size_t)ci * 9 + k];
        }
        __syncthreads();

        // 4x4 input window into registers
        float xin[4][4];
#pragma unroll
        for (int iy = 0; iy < 4; iy++)
#pragma unroll
            for (int ix = 0; ix < 4; ix++)
                xin[iy][ix] = s_in[ty * 2 + iy][tx * 2 + ix];

#pragma unroll
        for (int k = 0; k < 9; k++) {
            const int ky = k / 3, kx = k - ky * 3;
            float4 wa = *(const float4*)&s_w[k][cg * 8];
            float4 wb = *(const float4*)&s_w[k][cg * 8 + 4];
            float w[8] = {wa.x, wa.y, wa.z, wa.w, wb.x, wb.y, wb.z, wb.w};
#pragma unroll
            for (int j = 0; j < 8; j++)
#pragma unroll
                for (int py = 0; py < 2; py++)
#pragma unroll
                    for (int px = 0; px < 2; px++)
                        acc[j][py * 2 + px] =
                            fmaf(xin[py + ky][px + kx], w[j], acc[j][py * 2 + px]);
        }
        __syncthreads();
    }

    // epilogue: BN + ReLU, coalesced float2 stores (ox is even, W even)
#pragma unroll
    for (int j = 0; j < 8; j++) {
        const int co = coThr + j;
        const float s = scale[co], b = bias[co];
        size_t base = (((size_t)n * C + co) * H + oy) * W + ox;
        float2 r0, r1;
        r0.x = fmaxf(fmaf(acc[j][0], s, b), 0.f);
        r0.y = fmaxf(fmaf(acc[j][1], s, b), 0.f);
        r1.x = fmaxf(fmaf(acc[j][2], s, b), 0.f);
        r1.y = fmaxf(fmaf(acc[j][3], s, b), 0.f);
        *(float2*)&out[base]     = r0;
        *(float2*)&out[base + W] = r1;
    }
}

// ---------------------------------------------------------------------------
// conv1x1 (C -> 5) + bias + anchor decode + sigmoid
// ---------------------------------------------------------------------------
__global__ void __launch_bounds__(256)
conv1x1_decode_kernel(const float* __restrict__ y,
                      const float* __restrict__ wf,   // (5, C)
                      const float* __restrict__ bf,   // (5,)
                      float* __restrict__ out,
                      int C, int W, int HW, int aoff, float stride)
{
    extern __shared__ float s_wf[];  // 5*C floats
    for (int t = threadIdx.x; t < 5 * C; t += blockDim.x)
        s_wf[t] = wf[t];
    __syncthreads();

    const int p = blockIdx.x * blockDim.x + threadIdx.x;
    const int n = blockIdx.y;
    if (p >= HW) return;

    const float* yp = y + (size_t)n * C * HW + p;
    float a0 = bf[0], a1 = bf[1], a2 = bf[2], a3 = bf[3], a4 = bf[4];
    for (int ci = 0; ci < C; ci++) {
        float v = yp[(size_t)ci * HW];
        a0 = fmaf(v, s_wf[ci],         a0);
        a1 = fmaf(v, s_wf[C + ci],     a1);
        a2 = fmaf(v, s_wf[2 * C + ci], a2);
        a3 = fmaf(v, s_wf[3 * C + ci], a3);
        a4 = fmaf(v, s_wf[4 * C + ci], a4);
    }

    const int py = p / W;
    const int px = p - py * W;
    const float ax = px + 0.5f, ay = py + 0.5f;
    const float cx = (ax + 0.5f * (a2 - a0)) * stride;
    const float cy = (ay + 0.5f * (a3 - a1)) * stride;
    const float bw = (a2 + a0) * stride;
    const float bh = (a3 + a1) * stride;
    const float cls = 1.f / (1.f + expf(-a4));

    size_t base = (size_t)n * 5 * ATOT + (size_t)aoff + p;
    out[base]                    = cx;
    out[base + (size_t)ATOT]     = cy;
    out[base + 2 * (size_t)ATOT] = bw;
    out[base + 3 * (size_t)ATOT] = bh;
    out[base + 4 * (size_t)ATOT] = cls;
}

// ---------------------------------------------------------------------------
// Host side
// ---------------------------------------------------------------------------
template<int TW, int TH, int CG>
static void run_head_t(const float* x, void* const* d_in, int widx,
                       float* buf1, float* buf2, float* out,
                       int B, int C, int H, int aoff, float stride)
{
    const float* w1 = (const float*)d_in[widx + 0];
    const float* s1 = (const float*)d_in[widx + 1];
    const float* b1 = (const float*)d_in[widx + 2];
    const float* w2 = (const float*)d_in[widx + 3];
    const float* s2 = (const float*)d_in[widx + 4];
    const float* b2 = (const float*)d_in[widx + 5];
    const float* wf = (const float*)d_in[widx + 6];
    const float* bf = (const float*)d_in[widx + 7];

    const int W = H;
    const int tilesX = W / TW;
    const int tilesY = H / TH;
    const int COB = CG * 8;
    dim3 grid(tilesX * tilesY, C / COB, B);

    conv3x3_bn_relu_v2<TW, TH, CG><<<grid, 256>>>(x,    w1, s1, b1, buf1, C, H, W, tilesX);
    conv3x3_bn_relu_v2<TW, TH, CG><<<grid, 256>>>(buf1, w2, s2, b2, buf2, C, H, W, tilesX);

    const int HW = H * W;
    dim3 g2((HW + 255) / 256, B);
    conv1x1_decode_kernel<<<g2, 256, 5 * C * (int)sizeof(float)>>>(
        buf2, wf, bf, out, C, W, HW, aoff, stride);
}

extern "C" void kernel_launch(void* const* d_in, const int* in_sizes, int n_in,
                              void* d_out, int out_size)
{
    float *buf1, *buf2;
    cudaGetSymbolAddress((void**)&buf1, g_buf1);
    cudaGetSymbolAddress((void**)&buf2, g_buf2);

    const int B = in_sizes[0] / (128 * 160 * 160);
    float* out = (float*)d_out;

    // p3: 160x160, C=128 -> tile 32x16, 2 co-groups (16 couts/block)
    run_head_t<32, 16, 2>((const float*)d_in[0], d_in,  3, buf1, buf2, out, B, 128, 160, 0,     8.f);
    // p4: 80x80, C=256 -> tile 16x16, 4 co-groups (32 couts/block)
    run_head_t<16, 16, 4>((const float*)d_in[1], d_in, 11, buf1, buf2, out, B, 256,  80, 25600, 16.f);
    // p5: 40x40, C=512 -> tile 8x8, 16 co-groups (128 couts/block)
    run_head_t< 8,  8, 16>((const float*)d_in[2], d_in, 19, buf1, buf2, out, B, 512,  40, 32000, 32.f);
}

// round 4
// speedup vs baseline: 11.0056x; 5.0959x over previous
#include <cuda_runtime.h>
#include <math.h>
#include <stdint.h>

// ===========================================================================
// YOLOv8 head via tf32 mma.sync implicit GEMM (shifted-GEMM conv).
//   conv3x3(pad1) == sum over 9 kernel offsets k of GEMM:
//      D[co, p] += W_k[co, ci] * Xpad[p + off_k, ci]
//   Xpad pixel-major [pixel][ci], zero borders, guard slack for shifts.
// mma.sync.m16n8k8 tf32 is baseline PTX (compute_80+) -> works on compute_103.
// ===========================================================================

#define ATOT 33600

#define GUARD 262144
__device__ __align__(256) float g_xpad[2 * GUARD + 8 * 26244 * 128];
__device__ __align__(256) float g_ypad[2 * GUARD + 8 * 26244 * 128];
__device__ __align__(256) float g_y2  [8 * 25600 * 128];
__device__ __align__(256) float g_wr1 [9 * 512 * 512];
__device__ __align__(256) float g_wr2 [9 * 512 * 512];

__device__ __forceinline__ uint32_t smem_u32(const void* p) {
    return (uint32_t)__cvta_generic_to_shared(p);
}
__device__ __forceinline__ float tf32r(float v) {
    uint32_t r;
    asm("cvt.rna.tf32.f32 %0, %1;" : "=r"(r) : "f"(v));
    return __uint_as_float(r);
}
__device__ __forceinline__ void cp_async16(uint32_t dst, const float* src) {
    asm volatile("cp.async.cg.shared.global [%0], [%1], 16;"
                 :: "r"(dst), "l"(__cvta_generic_to_global(src)) : "memory");
}
__device__ __forceinline__ void cp_commit() {
    asm volatile("cp.async.commit_group;" ::: "memory");
}

__device__ __forceinline__ void mma_tf32(float& d0, float& d1, float& d2, float& d3,
                                         uint32_t a0, uint32_t a1, uint32_t a2, uint32_t a3,
                                         uint32_t b0, uint32_t b1) {
    asm volatile(
        "mma.sync.aligned.m16n8k8.row.col.f32.tf32.tf32.f32 "
        "{%0,%1,%2,%3}, {%4,%5,%6,%7}, {%8,%9}, {%0,%1,%2,%3};"
        : "+f"(d0), "+f"(d1), "+f"(d2), "+f"(d3)
        : "r"(a0), "r"(a1), "r"(a2), "r"(a3), "r"(b0), "r"(b1));
}

// ---------------------------------------------------------------------------
// weight repack: W(co,ci,3,3) fp32 -> Wrep[k][co][ci] tf32-rounded
// ---------------------------------------------------------------------------
__global__ void wrepack_kernel(const float* __restrict__ w, float* __restrict__ wr, int C)
{
    int idx = blockIdx.x * blockDim.x + threadIdx.x;   // co*C + ci
    if (idx >= C * C) return;
#pragma unroll
    for (int k = 0; k < 9; k++)
        wr[(size_t)k * C * C + idx] = tf32r(w[(size_t)idx * 9 + k]);
}

// ---------------------------------------------------------------------------
// zero border pixels of padded [Np][C] image blocks
// ---------------------------------------------------------------------------
__global__ void zero_border_kernel(float* __restrict__ Xp, int C, int Wp, int Np)
{
    int idx = blockIdx.x * blockDim.x + threadIdx.x;
    int nvec = C >> 2;
    if (idx >= Np * nvec) return;
    int p = idx / nvec;
    int py = p / Wp, px = p - py * Wp;
    if (py == 0 || py == Wp - 1 || px == 0 || px == Wp - 1) {
        float4 z = make_float4(0.f, 0.f, 0.f, 0.f);
        ((float4*)(Xp + (size_t)blockIdx.y * Np * C))[idx] = z;
    }
}

// ---------------------------------------------------------------------------
// pad+transpose+round: NCHW fp32 -> Xpad[n][p][ci] tf32 (interior only)
// ---------------------------------------------------------------------------
__global__ void pad_transpose_kernel(const float* __restrict__ in, float* __restrict__ Xp,
                                     int C, int H, int W, int Wp, int Np)
{
    __shared__ float t[32][33];
    const int HW = H * W;
    const int q0 = blockIdx.x * 32;
    const int c0 = blockIdx.y * 32;
    const int n  = blockIdx.z;
    const int tx = threadIdx.x, ty = threadIdx.y;

    const float* inN = in + (size_t)n * C * HW;
#pragma unroll
    for (int j = 0; j < 4; j++) {
        int c = c0 + ty + j * 8;
        t[ty + j * 8][tx] = tf32r(inN[(size_t)c * HW + q0 + tx]);
    }
    __syncthreads();
    float* XpN = Xp + (size_t)n * Np * C;
#pragma unroll
    for (int j = 0; j < 4; j++) {
        int q = q0 + ty + j * 8;
        int py = q / W, px = q - py * W;
        int p = (py + 1) * Wp + px + 1;
        XpN[(size_t)p * C + c0 + tx] = t[tx][ty + j * 8];
    }
}

// ---------------------------------------------------------------------------
// conv GEMM: D[128 co x 128 px] = sum_{k,ci} Wrep_k * Xpad(+off_k)
// 256 threads = 8 warps (2 M x 4 N), warp tile 64x32, mma m16n8k8 tf32.
// smem: A/B stages 128x32 fp32, padded stride 36, double buffered.
// mode 0: store padded [p][co] tf32 (feeds conv2); mode 1: [q][co] fp32.
// ---------------------------------------------------------------------------
#define KSTRIDE 36
#define STAGE   (128 * KSTRIDE)
#define OSTRIDE 132

__global__ void __launch_bounds__(256, 2)
conv_gemm_kernel(const float* __restrict__ X,
                 const float* __restrict__ wrep,
                 const float* __restrict__ scale,
                 const float* __restrict__ bias,
                 float* __restrict__ Y,
                 int C, int W, int Wp, int Np, int mode)
{
    extern __shared__ float dsm[];
    float* sA = dsm;              // 2 stages
    float* sB = dsm + 2 * STAGE;  // 2 stages

    const int tid    = threadIdx.x;
    const int lane   = tid & 31;
    const int wid    = tid >> 5;
    const int warp_m = wid >> 2;        // 0..1
    const int warp_n = wid & 3;         // 0..3
    const int p0     = blockIdx.x * 128;
    const int co0    = blockIdx.y * 128;
    const int n      = blockIdx.z;

    const float* Ximg = X + (size_t)n * Np * C;
    const int NC = 9 * (C >> 5);

    float acc[4][4][4];
#pragma unroll
    for (int mi = 0; mi < 4; mi++)
#pragma unroll
        for (int ni = 0; ni < 4; ni++)
#pragma unroll
            for (int r = 0; r < 4; r++) acc[mi][ni][r] = 0.f;

    // per-thread cp.async source/dest decomposition: e = tid + i*256
    // r = e>>3 (row 0..127), f = e&7 (float4 within 32-float row)
    auto load_chunk = [&](int c, int buf) {
        const int k   = c % 9;
        const int cic = c / 9;
        const int off = (k / 3 - 1) * Wp + (k % 3 - 1);
        const float* Asrc = wrep + ((size_t)k * C + co0) * C + cic * 32;
        const float* Bsrc = Ximg + (long long)(p0 + off) * C + cic * 32;
        float* sAb = sA + buf * STAGE;
        float* sBb = sB + buf * STAGE;
#pragma unroll
        for (int i = 0; i < 4; i++) {
            int e = tid + i * 256, r = e >> 3, f = e & 7;
            cp_async16(smem_u32(sAb + r * KSTRIDE + f * 4), Asrc + (size_t)r * C + f * 4);
            cp_async16(smem_u32(sBb + r * KSTRIDE + f * 4), Bsrc + (long long)r * C + f * 4);
        }
        cp_commit();
    };

    load_chunk(0, 0);

    for (int c = 0; c < NC; c++) {
        const int buf = c & 1;
        if (c + 1 < NC) {
            load_chunk(c + 1, buf ^ 1);
            asm volatile("cp.async.wait_group 1;" ::: "memory");
        } else {
            asm volatile("cp.async.wait_group 0;" ::: "memory");
        }
        __syncthreads();

        const float* sAb = sA + buf * STAGE;
        const float* sBb = sB + buf * STAGE;
        const int g = lane >> 2;
        const int kq = lane & 3;

#pragma unroll
        for (int ks = 0; ks < 4; ks++) {
            const int kb = ks * 8 + kq;
            uint32_t af[4][4], bf[4][2];
#pragma unroll
            for (int mi = 0; mi < 4; mi++) {
                int row = warp_m * 64 + mi * 16 + g;
                af[mi][0] = __float_as_uint(sAb[row * KSTRIDE + kb]);
                af[mi][1] = __float_as_uint(sAb[(row + 8) * KSTRIDE + kb]);
                af[mi][2] = __float_as_uint(sAb[row * KSTRIDE + kb + 4]);
                af[mi][3] = __float_as_uint(sAb[(row + 8) * KSTRIDE + kb + 4]);
            }
#pragma unroll
            for (int ni = 0; ni < 4; ni++) {
                int px = warp_n * 32 + ni * 8 + g;
                bf[ni][0] = __float_as_uint(sBb[px * KSTRIDE + kb]);
                bf[ni][1] = __float_as_uint(sBb[px * KSTRIDE + kb + 4]);
            }
#pragma unroll
            for (int mi = 0; mi < 4; mi++)
#pragma unroll
                for (int ni = 0; ni < 4; ni++)
                    mma_tf32(acc[mi][ni][0], acc[mi][ni][1], acc[mi][ni][2], acc[mi][ni][3],
                             af[mi][0], af[mi][1], af[mi][2], af[mi][3],
                             bf[ni][0], bf[ni][1]);
        }
        __syncthreads();
    }

    // ---- epilogue: BN+ReLU, stage [px][co] tile in smem, coalesced store ----
    float* st = dsm;   // 128 x OSTRIDE, fits in the (now idle) stage buffers
    {
        const int g = lane >> 2;
        const int q2 = (lane & 3) << 1;
#pragma unroll
        for (int mi = 0; mi < 4; mi++) {
            const int col0 = warp_m * 64 + mi * 16 + g;       // local co
            const float s0 = __ldg(scale + co0 + col0), b0 = __ldg(bias + co0 + col0);
            const float s1 = __ldg(scale + co0 + col0 + 8), b1 = __ldg(bias + co0 + col0 + 8);
#pragma unroll
            for (int ni = 0; ni < 4; ni++) {
                const int pxl = warp_n * 32 + ni * 8 + q2;    // local px
                float v0 = fmaxf(fmaf(acc[mi][ni][0], s0, b0), 0.f);
                float v1 = fmaxf(fmaf(acc[mi][ni][1], s0, b0), 0.f);
                float v2 = fmaxf(fmaf(acc[mi][ni][2], s1, b1), 0.f);
                float v3 = fmaxf(fmaf(acc[mi][ni][3], s1, b1), 0.f);
                if (mode == 0) { v0 = tf32r(v0); v1 = tf32r(v1); v2 = tf32r(v2); v3 = tf32r(v3); }
                st[pxl * OSTRIDE + col0]           = v0;
                st[(pxl + 1) * OSTRIDE + col0]     = v1;
                st[pxl * OSTRIDE + col0 + 8]       = v2;
                st[(pxl + 1) * OSTRIDE + col0 + 8] = v3;
            }
        }
    }
    __syncthreads();

    float* Yimg = Y + (mode == 0 ? (size_t)n * Np * C
                                 : (size_t)n * (size_t)(W * W) * C);
#pragma unroll 1
    for (int i = 0; i < 16; i++) {
        int idx = tid + i * 256;
        int r = idx >> 5, f = idx & 31;
        int p = p0 + r;
        if (p < Np) {
            int py = p / Wp, px = p - py * Wp;
            if (py >= 1 && py <= W && px >= 1 && px <= W) {
                float4 v = *(const float4*)&st[r * OSTRIDE + f * 4];
                if (mode == 0)
                    *(float4*)&Yimg[(size_t)p * C + co0 + f * 4] = v;
                else
                    *(float4*)&Yimg[((size_t)(py - 1) * W + (px - 1)) * C + co0 + f * 4] = v;
            }
        }
    }
}

// ---------------------------------------------------------------------------
// 1x1 conv (C->5) + decode + sigmoid. warp-per-pixel, y2 layout [n][q][C].
// ---------------------------------------------------------------------------
__global__ void __launch_bounds__(256)
conv1x1_decode_kernel(const float* __restrict__ y2,
                      const float* __restrict__ wf,
                      const float* __restrict__ bf,
                      float* __restrict__ out,
                      int C, int W, int HW, int aoff, float stride)
{
    __shared__ float s_wf[5 * 512];
    for (int t = threadIdx.x; t < 5 * C; t += 256) s_wf[t] = wf[t];
    __syncthreads();

    const int wid  = threadIdx.x >> 5;
    const int lane = threadIdx.x & 31;
    const int q = blockIdx.x * 8 + wid;
    const int n = blockIdx.y;
    if (q >= HW) return;

    const float* yq = y2 + ((size_t)n * HW + q) * C;
    float a[5] = {0.f, 0.f, 0.f, 0.f, 0.f};
    const int iters = C >> 7;
    for (int it = 0; it < iters; it++) {
        int cb = it * 128 + lane * 4;
        float4 v = *(const float4*)(yq + cb);
#pragma unroll
        for (int j = 0; j < 5; j++) {
            const float* wj = s_wf + j * C + cb;
            a[j] += v.x * wj[0] + v.y * wj[1] + v.z * wj[2] + v.w * wj[3];
        }
    }
#pragma unroll
    for (int j = 0; j < 5; j++)
#pragma unroll
        for (int o = 16; o; o >>= 1)
            a[j] += __shfl_xor_sync(0xffffffffu, a[j], o);

    if (lane == 0) {
        float a0 = a[0] + bf[0], a1 = a[1] + bf[1], a2 = a[2] + bf[2];
        float a3 = a[3] + bf[3], a4 = a[4] + bf[4];
        int py = q / W, px = q - py * W;
        float ax = px + 0.5f, ay = py + 0.5f;
        float cx = (ax + 0.5f * (a2 - a0)) * stride;
        float cy = (ay + 0.5f * (a3 - a1)) * stride;
        float bw = (a2 + a0) * stride;
        float bh = (a3 + a1) * stride;
        float cls = 1.f / (1.f + expf(-a4));
        size_t base = (size_t)n * 5 * ATOT + (size_t)aoff + q;
        out[base]                    = cx;
        out[base + (size_t)ATOT]     = cy;
        out[base + 2 * (size_t)ATOT] = bw;
        out[base + 3 * (size_t)ATOT] = bh;
        out[base + 4 * (size_t)ATOT] = cls;
    }
}

// ---------------------------------------------------------------------------
// Host
// ---------------------------------------------------------------------------
#define CONV_SMEM (4 * STAGE * (int)sizeof(float))   // 73728 B

static void run_level(void* const* d_in, int xin, int widx,
                      float* xpad, float* ypad, float* y2,
                      float* wr1, float* wr2, float* out,
                      int B, int C, int H, int aoff, float stride)
{
    const float* x  = (const float*)d_in[xin];
    const float* w1 = (const float*)d_in[widx + 0];
    const float* s1 = (const float*)d_in[widx + 1];
    const float* b1 = (const float*)d_in[widx + 2];
    const float* w2 = (const float*)d_in[widx + 3];
    const float* s2 = (const float*)d_in[widx + 4];
    const float* b2 = (const float*)d_in[widx + 5];
    const float* wf = (const float*)d_in[widx + 6];
    const float* bf = (const float*)d_in[widx + 7];

    const int W = H, Wp = W + 2, Np = Wp * Wp, HW = H * W;

    wrepack_kernel<<<(C * C + 255) / 256, 256>>>(w1, wr1, C);
    wrepack_kernel<<<(C * C + 255) / 256, 256>>>(w2, wr2, C);

    dim3 gz(((Np * (C >> 2)) + 255) / 256, B);
    zero_border_kernel<<<gz, 256>>>(xpad, C, Wp, Np);
    zero_border_kernel<<<gz, 256>>>(ypad, C, Wp, Np);

    dim3 gp(HW / 32, C / 32, B);
    pad_transpose_kernel<<<gp, dim3(32, 8)>>>(x, xpad, C, H, W, Wp, Np);

    const int pixTiles = (Np + 127) / 128;
    dim3 gc(pixTiles, C / 128, B);
    conv_gemm_kernel<<<gc, 256, CONV_SMEM>>>(xpad, wr1, s1, b1, ypad, C, W, Wp, Np, 0);
    conv_gemm_kernel<<<gc, 256, CONV_SMEM>>>(ypad, wr2, s2, b2, y2,   C, W, Wp, Np, 1);

    dim3 gd((HW + 7) / 8, B);
    conv1x1_decode_kernel<<<gd, 256>>>(y2, wf, bf, out, C, W, HW, aoff, stride);
}

extern "C" void kernel_launch(void* const* d_in, const int* in_sizes, int n_in,
                              void* d_out, int out_size)
{
    float *xpad, *ypad, *y2, *wr1, *wr2;
    cudaGetSymbolAddress((void**)&xpad, g_xpad);
    cudaGetSymbolAddress((void**)&ypad, g_ypad);
    cudaGetSymbolAddress((void**)&y2,   g_y2);
    cudaGetSymbolAddress((void**)&wr1,  g_wr1);
    cudaGetSymbolAddress((void**)&wr2,  g_wr2);
    xpad += GUARD;
    ypad += GUARD;

    cudaFuncSetAttribute(conv_gemm_kernel,
                         cudaFuncAttributeMaxDynamicSharedMemorySize, CONV_SMEM);

    const int B = in_sizes[0] / (128 * 160 * 160);
    float* out = (float*)d_out;

    run_level(d_in, 0,  3, xpad, ypad, y2, wr1, wr2, out, B, 128, 160, 0,     8.f);
    run_level(d_in, 1, 11, xpad, ypad, y2, wr1, wr2, out, B, 256,  80, 25600, 16.f);
    run_level(d_in, 2, 19, xpad, ypad, y2, wr1, wr2, out, B, 512,  40, 32000, 32.f);
}

// round 5
// speedup vs baseline: 20.2118x; 1.8365x over previous
#include <cuda_runtime.h>
#include <cuda_bf16.h>
#include <math.h>
#include <stdint.h>

// ===========================================================================
// YOLOv8 head via bf16 mma.sync implicit GEMM (shifted-GEMM conv).
//   conv3x3(pad1) == sum over 9 kernel offsets k of GEMM:
//      D[co, p] += W_k[co, ci] * Xpad[p + off_k, ci]
//   Xpad pixel-major [pixel][ci] bf16, zero borders (static zero-init, never
//   overwritten -> no runtime border zeroing), per-level disjoint regions.
// ===========================================================================

#define ATOT 33600
#define GUARDH 262144   // halves of slack between level regions

// per-level xpad/ypad region offsets (halves)
#define OFF_P3 262144
#define OFF_P4 27398144
#define OFF_P5 41431040
#define XPAD_TOTAL 48918528

__device__ __align__(256) __nv_bfloat16 g_xpad[XPAD_TOTAL];
__device__ __align__(256) __nv_bfloat16 g_ypad[XPAD_TOTAL];
__device__ __align__(256) float         g_y2  [8 * 25600 * 128];
__device__ __align__(256) __nv_bfloat16 g_wr1 [9 * 512 * 512];
__device__ __align__(256) __nv_bfloat16 g_wr2 [9 * 512 * 512];

__device__ __forceinline__ uint32_t smem_u32(const void* p) {
    return (uint32_t)__cvta_generic_to_shared(p);
}
__device__ __forceinline__ void cp_async16(uint32_t dst, const void* src) {
    asm volatile("cp.async.cg.shared.global [%0], [%1], 16;"
                 :: "r"(dst), "l"(__cvta_generic_to_global(src)) : "memory");
}
__device__ __forceinline__ void cp_commit() {
    asm volatile("cp.async.commit_group;" ::: "memory");
}

__device__ __forceinline__ void mma_bf16(float& d0, float& d1, float& d2, float& d3,
                                         uint32_t a0, uint32_t a1, uint32_t a2, uint32_t a3,
                                         uint32_t b0, uint32_t b1) {
    asm volatile(
        "mma.sync.aligned.m16n8k16.row.col.f32.bf16.bf16.f32 "
        "{%0,%1,%2,%3}, {%4,%5,%6,%7}, {%8,%9}, {%0,%1,%2,%3};"
        : "+f"(d0), "+f"(d1), "+f"(d2), "+f"(d3)
        : "r"(a0), "r"(a1), "r"(a2), "r"(a3), "r"(b0), "r"(b1));
}

// ---------------------------------------------------------------------------
// weight repack: W(co,ci,3,3) fp32 -> Wrep[k][co][ci] bf16
// ---------------------------------------------------------------------------
__global__ void wrepack_kernel(const float* __restrict__ w,
                               __nv_bfloat16* __restrict__ wr, int C)
{
    int idx = blockIdx.x * blockDim.x + threadIdx.x;   // co*C + ci
    if (idx >= C * C) return;
#pragma unroll
    for (int k = 0; k < 9; k++)
        wr[(size_t)k * C * C + idx] = __float2bfloat16_rn(w[(size_t)idx * 9 + k]);
}

// ---------------------------------------------------------------------------
// pad+transpose: NCHW fp32 -> Xpad[n][p][ci] bf16 (interior pixels only)
// ---------------------------------------------------------------------------
__global__ void pad_transpose_kernel(const float* __restrict__ in,
                                     __nv_bfloat16* __restrict__ Xp,
                                     int C, int H, int W, int Wp, int Np)
{
    __shared__ float t[32][33];
    const int HW = H * W;
    const int q0 = blockIdx.x * 32;
    const int c0 = blockIdx.y * 32;
    const int n  = blockIdx.z;
    const int tx = threadIdx.x, ty = threadIdx.y;

    const float* inN = in + (size_t)n * C * HW;
#pragma unroll
    for (int j = 0; j < 4; j++) {
        int c = c0 + ty + j * 8;
        t[ty + j * 8][tx] = inN[(size_t)c * HW + q0 + tx];
    }
    __syncthreads();
    __nv_bfloat16* XpN = Xp + (size_t)n * Np * C;
#pragma unroll
    for (int j = 0; j < 4; j++) {
        int q = q0 + ty + j * 8;
        int py = q / W, px = q - py * W;
        int p = (py + 1) * Wp + px + 1;
        XpN[(size_t)p * C + c0 + tx] = __float2bfloat16_rn(t[tx][ty + j * 8]);
    }
}

// ---------------------------------------------------------------------------
// conv GEMM: D[128 co x 128 px] = sum_{k,ci} Wrep_k * Xpad(+off_k)
// 8 warps (2 M x 4 N), warp tile 64x32, mma m16n8k16 bf16, K-chunk 64,
// cp.async double-buffered. mode 0: bf16 padded [p][co]; mode 1: fp32 [q][co].
// ---------------------------------------------------------------------------
#define KS      72                      // halves per smem row (64 + 8 pad)
#define STAGEH  (128 * KS)              // halves per stage
#define OSTRIDE 132

__global__ void __launch_bounds__(256, 2)
conv_gemm_kernel(const __nv_bfloat16* __restrict__ X,
                 const __nv_bfloat16* __restrict__ wrep,
                 const float* __restrict__ scale,
                 const float* __restrict__ bias,
                 void* __restrict__ Yv,
                 int C, int W, int Wp, int Np, int mode)
{
    extern __shared__ __nv_bfloat16 dsm[];
    __nv_bfloat16* sA = dsm;               // 2 stages
    __nv_bfloat16* sB = dsm + 2 * STAGEH;  // 2 stages

    const int tid    = threadIdx.x;
    const int lane   = tid & 31;
    const int wid    = tid >> 5;
    const int warp_m = wid >> 2;
    const int warp_n = wid & 3;
    const int p0     = blockIdx.x * 128;
    const int co0    = blockIdx.y * 128;
    const int n      = blockIdx.z;

    const __nv_bfloat16* Ximg = X + (size_t)n * Np * C;
    const int NC = 9 * (C >> 6);        // K-chunks of 64 ci

    float acc[4][4][4];
#pragma unroll
    for (int mi = 0; mi < 4; mi++)
#pragma unroll
        for (int ni = 0; ni < 4; ni++)
#pragma unroll
            for (int r = 0; r < 4; r++) acc[mi][ni][r] = 0.f;

    auto load_chunk = [&](int c, int buf) {
        const int k   = c % 9;
        const int cic = c / 9;
        const int off = (k / 3 - 1) * Wp + (k % 3 - 1);
        const __nv_bfloat16* Asrc = wrep + ((size_t)k * C + co0) * C + cic * 64;
        const __nv_bfloat16* Bsrc = Ximg + (long long)(p0 + off) * C + cic * 64;
        __nv_bfloat16* sAb = sA + buf * STAGEH;
        __nv_bfloat16* sBb = sB + buf * STAGEH;
#pragma unroll
        for (int i = 0; i < 4; i++) {
            int e = tid + i * 256, r = e >> 3, f = e & 7;  // 128 rows x 8 groups of 8 halves
            cp_async16(smem_u32(sAb + r * KS + f * 8), Asrc + (size_t)r * C + f * 8);
            cp_async16(smem_u32(sBb + r * KS + f * 8), Bsrc + (long long)r * C + f * 8);
        }
        cp_commit();
    };

    load_chunk(0, 0);

    const int g  = lane >> 2;
    const int kq = lane & 3;

    for (int c = 0; c < NC; c++) {
        const int buf = c & 1;
        if (c + 1 < NC) {
            load_chunk(c + 1, buf ^ 1);
            asm volatile("cp.async.wait_group 1;" ::: "memory");
        } else {
            asm volatile("cp.async.wait_group 0;" ::: "memory");
        }
        __syncthreads();

        const __nv_bfloat16* sAb = sA + buf * STAGEH;
        const __nv_bfloat16* sBb = sB + buf * STAGEH;

#pragma unroll
        for (int ks = 0; ks < 4; ks++) {
            const int kb = ks * 16 + 2 * kq;   // even -> 4B aligned
            uint32_t af[4][4], bf[4][2];
#pragma unroll
            for (int mi = 0; mi < 4; mi++) {
                int row = warp_m * 64 + mi * 16 + g;
                af[mi][0] = *(const uint32_t*)&sAb[row * KS + kb];
                af[mi][1] = *(const uint32_t*)&sAb[(row + 8) * KS + kb];
                af[mi][2] = *(const uint32_t*)&sAb[row * KS + kb + 8];
                af[mi][3] = *(const uint32_t*)&sAb[(row + 8) * KS + kb + 8];
            }
#pragma unroll
            for (int ni = 0; ni < 4; ni++) {
                int px = warp_n * 32 + ni * 8 + g;
                bf[ni][0] = *(const uint32_t*)&sBb[px * KS + kb];
                bf[ni][1] = *(const uint32_t*)&sBb[px * KS + kb + 8];
            }
#pragma unroll
            for (int mi = 0; mi < 4; mi++)
#pragma unroll
                for (int ni = 0; ni < 4; ni++)
                    mma_bf16(acc[mi][ni][0], acc[mi][ni][1], acc[mi][ni][2], acc[mi][ni][3],
                             af[mi][0], af[mi][1], af[mi][2], af[mi][3],
                             bf[ni][0], bf[ni][1]);
        }
        __syncthreads();
    }

    // ---- epilogue: BN+ReLU, stage [px][co] fp32 tile in smem ----
    float* st = (float*)dsm;
    {
        const int q2 = kq << 1;
#pragma unroll
        for (int mi = 0; mi < 4; mi++) {
            const int col0 = warp_m * 64 + mi * 16 + g;
            const float s0 = __ldg(scale + co0 + col0),     b0 = __ldg(bias + co0 + col0);
            const float s1 = __ldg(scale + co0 + col0 + 8), b1 = __ldg(bias + co0 + col0 + 8);
#pragma unroll
            for (int ni = 0; ni < 4; ni++) {
                const int pxl = warp_n * 32 + ni * 8 + q2;
                st[pxl * OSTRIDE + col0]           = fmaxf(fmaf(acc[mi][ni][0], s0, b0), 0.f);
                st[(pxl + 1) * OSTRIDE + col0]     = fmaxf(fmaf(acc[mi][ni][1], s0, b0), 0.f);
                st[pxl * OSTRIDE + col0 + 8]       = fmaxf(fmaf(acc[mi][ni][2], s1, b1), 0.f);
                st[(pxl + 1) * OSTRIDE + col0 + 8] = fmaxf(fmaf(acc[mi][ni][3], s1, b1), 0.f);
            }
        }
    }
    __syncthreads();

#pragma unroll 1
    for (int i = 0; i < 16; i++) {
        int idx = tid + i * 256;
        int r = idx >> 5, f = idx & 31;
        int p = p0 + r;
        if (p < Np) {
            int py = p / Wp, px = p - py * Wp;
            if (py >= 1 && py <= W && px >= 1 && px <= W) {
                float4 v = *(const float4*)&st[r * OSTRIDE + f * 4];
                if (mode == 0) {
                    __nv_bfloat16* Yb = (__nv_bfloat16*)Yv + (size_t)n * Np * C;
                    __nv_bfloat162 h0 = __floats2bfloat162_rn(v.x, v.y);
                    __nv_bfloat162 h1 = __floats2bfloat162_rn(v.z, v.w);
                    uint2 pk;
                    pk.x = *reinterpret_cast<uint32_t*>(&h0);
                    pk.y = *reinterpret_cast<uint32_t*>(&h1);
                    *(uint2*)&Yb[(size_t)p * C + co0 + f * 4] = pk;
                } else {
                    float* Yf = (float*)Yv + (size_t)n * (size_t)(W * W) * C;
                    *(float4*)&Yf[((size_t)(py - 1) * W + (px - 1)) * C + co0 + f * 4] = v;
                }
            }
        }
    }
}

// ---------------------------------------------------------------------------
// 1x1 conv (C->5) + decode + sigmoid. warp-per-pixel, y2 layout [n][q][C].
// ---------------------------------------------------------------------------
__global__ void __launch_bounds__(256)
conv1x1_decode_kernel(const float* __restrict__ y2,
                      const float* __restrict__ wf,
                      const float* __restrict__ bf,
                      float* __restrict__ out,
                      int C, int W, int HW, int aoff, float stride)
{
    __shared__ float s_wf[5 * 512];
    for (int t = threadIdx.x; t < 5 * C; t += 256) s_wf[t] = wf[t];
    __syncthreads();

    const int wid  = threadIdx.x >> 5;
    const int lane = threadIdx.x & 31;
    const int q = blockIdx.x * 8 + wid;
    const int n = blockIdx.y;
    if (q >= HW) return;

    const float* yq = y2 + ((size_t)n * HW + q) * C;
    float a[5] = {0.f, 0.f, 0.f, 0.f, 0.f};
    const int iters = C >> 7;
    for (int it = 0; it < iters; it++) {
        int cb = it * 128 + lane * 4;
        float4 v = *(const float4*)(yq + cb);
#pragma unroll
        for (int j = 0; j < 5; j++) {
            const float* wj = s_wf + j * C + cb;
            a[j] += v.x * wj[0] + v.y * wj[1] + v.z * wj[2] + v.w * wj[3];
        }
    }
#pragma unroll
    for (int j = 0; j < 5; j++)
#pragma unroll
        for (int o = 16; o; o >>= 1)
            a[j] += __shfl_xor_sync(0xffffffffu, a[j], o);

    if (lane == 0) {
        float a0 = a[0] + bf[0], a1 = a[1] + bf[1], a2 = a[2] + bf[2];
        float a3 = a[3] + bf[3], a4 = a[4] + bf[4];
        int py = q / W, px = q - py * W;
        float ax = px + 0.5f, ay = py + 0.5f;
        float cx = (ax + 0.5f * (a2 - a0)) * stride;
        float cy = (ay + 0.5f * (a3 - a1)) * stride;
        float bw = (a2 + a0) * stride;
        float bh = (a3 + a1) * stride;
        float cls = 1.f / (1.f + expf(-a4));
        size_t base = (size_t)n * 5 * ATOT + (size_t)aoff + q;
        out[base]                    = cx;
        out[base + (size_t)ATOT]     = cy;
        out[base + 2 * (size_t)ATOT] = bw;
        out[base + 3 * (size_t)ATOT] = bh;
        out[base + 4 * (size_t)ATOT] = cls;
    }
}

// ---------------------------------------------------------------------------
// Host
// ---------------------------------------------------------------------------
#define CONV_SMEM (4 * STAGEH * 2)   // 73728 B (also covers 128*132*4 epilogue)

static void run_level(void* const* d_in, int xin, int widx,
                      __nv_bfloat16* xpad, __nv_bfloat16* ypad, float* y2,
                      __nv_bfloat16* wr1, __nv_bfloat16* wr2, float* out,
                      int B, int C, int H, int aoff, float stride)
{
    const float* x  = (const float*)d_in[xin];
    const float* w1 = (const float*)d_in[widx + 0];
    const float* s1 = (const float*)d_in[widx + 1];
    const float* b1 = (const float*)d_in[widx + 2];
    const float* w2 = (const float*)d_in[widx + 3];
    const float* s2 = (const float*)d_in[widx + 4];
    const float* b2 = (const float*)d_in[widx + 5];
    const float* wf = (const float*)d_in[widx + 6];
    const float* bf = (const float*)d_in[widx + 7];

    const int W = H, Wp = W + 2, Np = Wp * Wp, HW = H * W;

    wrepack_kernel<<<(C * C + 255) / 256, 256>>>(w1, wr1, C);
    wrepack_kernel<<<(C * C + 255) / 256, 256>>>(w2, wr2, C);

    dim3 gp(HW / 32, C / 32, B);
    pad_transpose_kernel<<<gp, dim3(32, 8)>>>(x, xpad, C, H, W, Wp, Np);

    const int pixTiles = (Np + 127) / 128;
    dim3 gc(pixTiles, C / 128, B);
    conv_gemm_kernel<<<gc, 256, CONV_SMEM>>>(xpad, wr1, s1, b1, ypad, C, W, Wp, Np, 0);
    conv_gemm_kernel<<<gc, 256, CONV_SMEM>>>(ypad, wr2, s2, b2, y2,   C, W, Wp, Np, 1);

    dim3 gd((HW + 7) / 8, B);
    conv1x1_decode_kernel<<<gd, 256>>>(y2, wf, bf, out, C, W, HW, aoff, stride);
}

extern "C" void kernel_launch(void* const* d_in, const int* in_sizes, int n_in,
                              void* d_out, int out_size)
{
    __nv_bfloat16 *xpad, *ypad, *wr1, *wr2;
    float *y2;
    cudaGetSymbolAddress((void**)&xpad, g_xpad);
    cudaGetSymbolAddress((void**)&ypad, g_ypad);
    cudaGetSymbolAddress((void**)&y2,   g_y2);
    cudaGetSymbolAddress((void**)&wr1,  g_wr1);
    cudaGetSymbolAddress((void**)&wr2,  g_wr2);

    cudaFuncSetAttribute(conv_gemm_kernel,
                         cudaFuncAttributeMaxDynamicSharedMemorySize, CONV_SMEM);

    const int B = in_sizes[0] / (128 * 160 * 160);
    float* out = (float*)d_out;

    run_level(d_in, 0,  3, xpad + OFF_P3, ypad + OFF_P3, y2, wr1, wr2, out, B, 128, 160, 0,     8.f);
    run_level(d_in, 1, 11, xpad + OFF_P4, ypad + OFF_P4, y2, wr1, wr2, out, B, 256,  80, 25600, 16.f);
    run_level(d_in, 2, 19, xpad + OFF_P5, ypad + OFF_P5, y2, wr1, wr2, out, B, 512,  40, 32000, 32.f);
}

// round 6
// speedup vs baseline: 22.1768x; 1.0972x over previous
#include <cuda_runtime.h>
#include <cuda_bf16.h>
#include <math.h>
#include <stdint.h>

// ===========================================================================
// YOLOv8 head via bf16 mma.sync implicit GEMM (shifted-GEMM conv).
//   conv3x3(pad1) == sum over 9 kernel offsets k of GEMM:
//      D[co, p] += W_k[co, ci] * Xpad[p + off_k, ci]
//   Xpad pixel-major [pixel][ci] bf16, zero borders (static zero-init, never
//   overwritten), per-level disjoint regions with guard slack.
// R6: ldmatrix fragment loads + 3-stage cp.async pipeline (1 sync/chunk).
// ===========================================================================

#define ATOT 33600

// per-level xpad/ypad region offsets (halves)
#define OFF_P3 262144
#define OFF_P4 27398144
#define OFF_P5 41431040
#define XPAD_TOTAL 48918528

__device__ __align__(256) __nv_bfloat16 g_xpad[XPAD_TOTAL];
__device__ __align__(256) __nv_bfloat16 g_ypad[XPAD_TOTAL];
__device__ __align__(256) float         g_y2  [8 * 25600 * 128];
__device__ __align__(256) __nv_bfloat16 g_wr1 [9 * 512 * 512];
__device__ __align__(256) __nv_bfloat16 g_wr2 [9 * 512 * 512];

__device__ __forceinline__ uint32_t smem_u32(const void* p) {
    return (uint32_t)__cvta_generic_to_shared(p);
}
__device__ __forceinline__ void cp_async16(uint32_t dst, const void* src) {
    asm volatile("cp.async.cg.shared.global [%0], [%1], 16;"
                 :: "r"(dst), "l"(__cvta_generic_to_global(src)) : "memory");
}
__device__ __forceinline__ void cp_commit() {
    asm volatile("cp.async.commit_group;" ::: "memory");
}
__device__ __forceinline__ void ldsm_x4(uint32_t& r0, uint32_t& r1,
                                        uint32_t& r2, uint32_t& r3, uint32_t a) {
    asm volatile("ldmatrix.sync.aligned.m8n8.x4.shared.b16 {%0,%1,%2,%3}, [%4];"
                 : "=r"(r0), "=r"(r1), "=r"(r2), "=r"(r3) : "r"(a));
}
__device__ __forceinline__ void mma_bf16(float& d0, float& d1, float& d2, float& d3,
                                         uint32_t a0, uint32_t a1, uint32_t a2, uint32_t a3,
                                         uint32_t b0, uint32_t b1) {
    asm volatile(
        "mma.sync.aligned.m16n8k16.row.col.f32.bf16.bf16.f32 "
        "{%0,%1,%2,%3}, {%4,%5,%6,%7}, {%8,%9}, {%0,%1,%2,%3};"
        : "+f"(d0), "+f"(d1), "+f"(d2), "+f"(d3)
        : "r"(a0), "r"(a1), "r"(a2), "r"(a3), "r"(b0), "r"(b1));
}

// ---------------------------------------------------------------------------
// weight repack: W(co,ci,3,3) fp32 -> Wrep[k][co][ci] bf16
// ---------------------------------------------------------------------------
__global__ void wrepack_kernel(const float* __restrict__ w,
                               __nv_bfloat16* __restrict__ wr, int C)
{
    int idx = blockIdx.x * blockDim.x + threadIdx.x;   // co*C + ci
    if (idx >= C * C) return;
#pragma unroll
    for (int k = 0; k < 9; k++)
        wr[(size_t)k * C * C + idx] = __float2bfloat16_rn(w[(size_t)idx * 9 + k]);
}

// ---------------------------------------------------------------------------
// pad+transpose: NCHW fp32 -> Xpad[n][p][ci] bf16 (interior pixels only)
// ---------------------------------------------------------------------------
__global__ void pad_transpose_kernel(const float* __restrict__ in,
                                     __nv_bfloat16* __restrict__ Xp,
                                     int C, int H, int W, int Wp, int Np)
{
    __shared__ float t[32][33];
    const int HW = H * W;
    const int q0 = blockIdx.x * 32;
    const int c0 = blockIdx.y * 32;
    const int n  = blockIdx.z;
    const int tx = threadIdx.x, ty = threadIdx.y;

    const float* inN = in + (size_t)n * C * HW;
#pragma unroll
    for (int j = 0; j < 4; j++) {
        int c = c0 + ty + j * 8;
        t[ty + j * 8][tx] = inN[(size_t)c * HW + q0 + tx];
    }
    __syncthreads();
    __nv_bfloat16* XpN = Xp + (size_t)n * Np * C;
#pragma unroll
    for (int j = 0; j < 4; j++) {
        int q = q0 + ty + j * 8;
        int py = q / W, px = q - py * W;
        int p = (py + 1) * Wp + px + 1;
        XpN[(size_t)p * C + c0 + tx] = __float2bfloat16_rn(t[tx][ty + j * 8]);
    }
}

// ---------------------------------------------------------------------------
// conv GEMM: D[128 co x 128 px] = sum_{k,ci} Wrep_k * Xpad(+off_k)
// 8 warps (2M x 4N), warp tile 64x32, mma m16n8k16 bf16, K-chunk 64,
// 3-stage cp.async pipeline, ldmatrix fragment loads.
// mode 0: bf16 padded [p][co]; mode 1: fp32 [q][co].
// ---------------------------------------------------------------------------
#define KS      72                      // halves per smem row (64 + 8 pad)
#define STAGEH  (2 * 128 * KS)          // halves per stage (A tile + B tile)
#define OSTRIDE 132

__global__ void __launch_bounds__(256, 2)
conv_gemm_kernel(const __nv_bfloat16* __restrict__ X,
                 const __nv_bfloat16* __restrict__ wrep,
                 const float* __restrict__ scale,
                 const float* __restrict__ bias,
                 void* __restrict__ Yv,
                 int C, int W, int Wp, int Np, int mode)
{
    extern __shared__ __nv_bfloat16 dsm[];   // 3 stages of [A(128xKS) | B(128xKS)]

    const int tid    = threadIdx.x;
    const int lane   = tid & 31;
    const int wid    = tid >> 5;
    const int warp_m = wid >> 2;
    const int warp_n = wid & 3;
    const int p0     = blockIdx.x * 128;
    const int co0    = blockIdx.y * 128;
    const int n      = blockIdx.z;

    const __nv_bfloat16* Ximg = X + (size_t)n * Np * C;
    const int NC = 9 * (C >> 6);        // K-chunks of 64 ci

    float acc[4][4][4];
#pragma unroll
    for (int mi = 0; mi < 4; mi++)
#pragma unroll
        for (int ni = 0; ni < 4; ni++)
#pragma unroll
            for (int r = 0; r < 4; r++) acc[mi][ni][r] = 0.f;

    const uint32_t smem0 = smem_u32(dsm);

    auto load_chunk = [&](int c, int buf) {
        const int k   = c % 9;
        const int cic = c / 9;
        const int off = (k / 3 - 1) * Wp + (k % 3 - 1);
        const __nv_bfloat16* Asrc = wrep + ((size_t)k * C + co0) * C + cic * 64;
        const __nv_bfloat16* Bsrc = Ximg + (long long)(p0 + off) * C + cic * 64;
        const uint32_t sAb = smem0 + buf * (STAGEH * 2);
        const uint32_t sBb = sAb + 128 * KS * 2;
#pragma unroll
        for (int i = 0; i < 4; i++) {
            int e = tid + i * 256, r = e >> 3, f = e & 7;  // 128 rows x 8 float4-of-halves
            cp_async16(sAb + (r * KS + f * 8) * 2, Asrc + (size_t)r * C + f * 8);
            cp_async16(sBb + (r * KS + f * 8) * 2, Bsrc + (long long)r * C + f * 8);
        }
        cp_commit();
    };

    // per-thread ldmatrix byte offsets (stage-relative)
    uint32_t aOff[4], bOff[2];
#pragma unroll
    for (int mi = 0; mi < 4; mi++) {
        int row = warp_m * 64 + mi * 16 + (lane & 15);
        aOff[mi] = (uint32_t)((row * KS + ((lane >> 4) << 3)) * 2);
    }
#pragma unroll
    for (int np = 0; np < 2; np++) {
        int px = warp_n * 32 + np * 16 + ((lane >> 4) << 3) + (lane & 7);
        bOff[np] = (uint32_t)((px * KS + (((lane >> 3) & 1) << 3)) * 2) + 128 * KS * 2;
    }

    load_chunk(0, 0);
    if (NC > 1) load_chunk(1, 1);

    int buf = 0;
    for (int c = 0; c < NC; c++) {
        if (c + 1 < NC)
            asm volatile("cp.async.wait_group 1;" ::: "memory");
        else
            asm volatile("cp.async.wait_group 0;" ::: "memory");
        __syncthreads();

        if (c + 2 < NC) {
            int nb = buf + 2; if (nb >= 3) nb -= 3;
            load_chunk(c + 2, nb);
        }

        const uint32_t sbase = smem0 + buf * (STAGEH * 2);
#pragma unroll
        for (int ks = 0; ks < 4; ks++) {
            const uint32_t ko = ks * 32;    // 16 halves
            uint32_t af[4][4], bf[2][4];
#pragma unroll
            for (int mi = 0; mi < 4; mi++)
                ldsm_x4(af[mi][0], af[mi][1], af[mi][2], af[mi][3],
                        sbase + aOff[mi] + ko);
#pragma unroll
            for (int np = 0; np < 2; np++)
                ldsm_x4(bf[np][0], bf[np][1], bf[np][2], bf[np][3],
                        sbase + bOff[np] + ko);
#pragma unroll
            for (int mi = 0; mi < 4; mi++)
#pragma unroll
                for (int ni = 0; ni < 4; ni++)
                    mma_bf16(acc[mi][ni][0], acc[mi][ni][1], acc[mi][ni][2], acc[mi][ni][3],
                             af[mi][0], af[mi][1], af[mi][2], af[mi][3],
                             bf[ni >> 1][(ni & 1) * 2], bf[ni >> 1][(ni & 1) * 2 + 1]);
        }
        buf++; if (buf == 3) buf = 0;
    }
    __syncthreads();

    // ---- epilogue: BN+ReLU, stage [px][co] fp32 tile in smem ----
    float* st = (float*)dsm;
    {
        const int g  = lane >> 2;
        const int q2 = (lane & 3) << 1;
#pragma unroll
        for (int mi = 0; mi < 4; mi++) {
            const int col0 = warp_m * 64 + mi * 16 + g;
            const float s0 = __ldg(scale + co0 + col0),     b0 = __ldg(bias + co0 + col0);
            const float s1 = __ldg(scale + co0 + col0 + 8), b1 = __ldg(bias + co0 + col0 + 8);
#pragma unroll
            for (int ni = 0; ni < 4; ni++) {
                const int pxl = warp_n * 32 + ni * 8 + q2;
                st[pxl * OSTRIDE + col0]           = fmaxf(fmaf(acc[mi][ni][0], s0, b0), 0.f);
                st[(pxl + 1) * OSTRIDE + col0]     = fmaxf(fmaf(acc[mi][ni][1], s0, b0), 0.f);
                st[pxl * OSTRIDE + col0 + 8]       = fmaxf(fmaf(acc[mi][ni][2], s1, b1), 0.f);
                st[(pxl + 1) * OSTRIDE + col0 + 8] = fmaxf(fmaf(acc[mi][ni][3], s1, b1), 0.f);
            }
        }
    }
    __syncthreads();

#pragma unroll 1
    for (int i = 0; i < 16; i++) {
        int idx = tid + i * 256;
        int r = idx >> 5, f = idx & 31;
        int p = p0 + r;
        if (p < Np) {
            int py = p / Wp, px = p - py * Wp;
            if (py >= 1 && py <= W && px >= 1 && px <= W) {
                float4 v = *(const float4*)&st[r * OSTRIDE + f * 4];
                if (mode == 0) {
                    __nv_bfloat16* Yb = (__nv_bfloat16*)Yv + (size_t)n * Np * C;
                    __nv_bfloat162 h0 = __floats2bfloat162_rn(v.x, v.y);
                    __nv_bfloat162 h1 = __floats2bfloat162_rn(v.z, v.w);
                    uint2 pk;
                    pk.x = *reinterpret_cast<uint32_t*>(&h0);
                    pk.y = *reinterpret_cast<uint32_t*>(&h1);
                    *(uint2*)&Yb[(size_t)p * C + co0 + f * 4] = pk;
                } else {
                    float* Yf = (float*)Yv + (size_t)n * (size_t)(W * W) * C;
                    *(float4*)&Yf[((size_t)(py - 1) * W + (px - 1)) * C + co0 + f * 4] = v;
                }
            }
        }
    }
}

// ---------------------------------------------------------------------------
// 1x1 conv (C->5) + decode + sigmoid. warp-per-pixel, y2 layout [n][q][C].
// ---------------------------------------------------------------------------
__global__ void __launch_bounds__(256)
conv1x1_decode_kernel(const float* __restrict__ y2,
                      const float* __restrict__ wf,
                      const float* __restrict__ bf,
                      float* __restrict__ out,
                      int C, int W, int HW, int aoff, float stride)
{
    __shared__ float s_wf[5 * 512];
    for (int t = threadIdx.x; t < 5 * C; t += 256) s_wf[t] = wf[t];
    __syncthreads();

    const int wid  = threadIdx.x >> 5;
    const int lane = threadIdx.x & 31;
    const int q = blockIdx.x * 8 + wid;
    const int n = blockIdx.y;
    if (q >= HW) return;

    const float* yq = y2 + ((size_t)n * HW + q) * C;
    float a[5] = {0.f, 0.f, 0.f, 0.f, 0.f};
    const int iters = C >> 7;
    for (int it = 0; it < iters; it++) {
        int cb = it * 128 + lane * 4;
        float4 v = *(const float4*)(yq + cb);
#pragma unroll
        for (int j = 0; j < 5; j++) {
            const float* wj = s_wf + j * C + cb;
            a[j] += v.x * wj[0] + v.y * wj[1] + v.z * wj[2] + v.w * wj[3];
        }
    }
#pragma unroll
    for (int j = 0; j < 5; j++)
#pragma unroll
        for (int o = 16; o; o >>= 1)
            a[j] += __shfl_xor_sync(0xffffffffu, a[j], o);

    if (lane == 0) {
        float a0 = a[0] + bf[0], a1 = a[1] + bf[1], a2 = a[2] + bf[2];
        float a3 = a[3] + bf[3], a4 = a[4] + bf[4];
        int py = q / W, px = q - py * W;
        float ax = px + 0.5f, ay = py + 0.5f;
        float cx = (ax + 0.5f * (a2 - a0)) * stride;
        float cy = (ay + 0.5f * (a3 - a1)) * stride;
        float bw = (a2 + a0) * stride;
        float bh = (a3 + a1) * stride;
        float cls = 1.f / (1.f + expf(-a4));
        size_t base = (size_t)n * 5 * ATOT + (size_t)aoff + q;
        out[base]                    = cx;
        out[base + (size_t)ATOT]     = cy;
        out[base + 2 * (size_t)ATOT] = bw;
        out[base + 3 * (size_t)ATOT] = bh;
        out[base + 4 * (size_t)ATOT] = cls;
    }
}

// ---------------------------------------------------------------------------
// Host
// ---------------------------------------------------------------------------
#define CONV_SMEM (3 * STAGEH * 2)   // 110592 B

static void run_level(void* const* d_in, int xin, int widx,
                      __nv_bfloat16* xpad, __nv_bfloat16* ypad, float* y2,
                      __nv_bfloat16* wr1, __nv_bfloat16* wr2, float* out,
                      int B, int C, int H, int aoff, float stride)
{
    const float* x  = (const float*)d_in[xin];
    const float* w1 = (const float*)d_in[widx + 0];
    const float* s1 = (const float*)d_in[widx + 1];
    const float* b1 = (const float*)d_in[widx + 2];
    const float* w2 = (const float*)d_in[widx + 3];
    const float* s2 = (const float*)d_in[widx + 4];
    const float* b2 = (const float*)d_in[widx + 5];
    const float* wf = (const float*)d_in[widx + 6];
    const float* bf = (const float*)d_in[widx + 7];

    const int W = H, Wp = W + 2, Np = Wp * Wp, HW = H * W;

    wrepack_kernel<<<(C * C + 255) / 256, 256>>>(w1, wr1, C);
    wrepack_kernel<<<(C * C + 255) / 256, 256>>>(w2, wr2, C);

    dim3 gp(HW / 32, C / 32, B);
    pad_transpose_kernel<<<gp, dim3(32, 8)>>>(x, xpad, C, H, W, Wp, Np);

    const int pixTiles = (Np + 127) / 128;
    dim3 gc(pixTiles, C / 128, B);
    conv_gemm_kernel<<<gc, 256, CONV_SMEM>>>(xpad, wr1, s1, b1, ypad, C, W, Wp, Np, 0);
    conv_gemm_kernel<<<gc, 256, CONV_SMEM>>>(ypad, wr2, s2, b2, y2,   C, W, Wp, Np, 1);

    dim3 gd((HW + 7) / 8, B);
    conv1x1_decode_kernel<<<gd, 256>>>(y2, wf, bf, out, C, W, HW, aoff, stride);
}

extern "C" void kernel_launch(void* const* d_in, const int* in_sizes, int n_in,
                              void* d_out, int out_size)
{
    __nv_bfloat16 *xpad, *ypad, *wr1, *wr2;
    float *y2;
    cudaGetSymbolAddress((void**)&xpad, g_xpad);
    cudaGetSymbolAddress((void**)&ypad, g_ypad);
    cudaGetSymbolAddress((void**)&y2,   g_y2);
    cudaGetSymbolAddress((void**)&wr1,  g_wr1);
    cudaGetSymbolAddress((void**)&wr2,  g_wr2);

    cudaFuncSetAttribute(conv_gemm_kernel,
                         cudaFuncAttributeMaxDynamicSharedMemorySize, CONV_SMEM);

    const int B = in_sizes[0] / (128 * 160 * 160);
    float* out = (float*)d_out;

    run_level(d_in, 0,  3, xpad + OFF_P3, ypad + OFF_P3, y2, wr1, wr2, out, B, 128, 160, 0,     8.f);
    run_level(d_in, 1, 11, xpad + OFF_P4, ypad + OFF_P4, y2, wr1, wr2, out, B, 256,  80, 25600, 16.f);
    run_level(d_in, 2, 19, xpad + OFF_P5, ypad + OFF_P5, y2, wr1, wr2, out, B, 512,  40, 32000, 32.f);
}